// round 13
// baseline (speedup 1.0000x reference)
#include <cuda_runtime.h>
#include <cuda_fp16.h>
#include <cstdint>

// ---------------------------------------------------------------------------
// DigitConvolutionalModel via mma.sync fp16 GEMMs (single fp16 weights).
// R13 = R12 with the smem-size bug fixed (bias lived above both double
// buffers at byte 81920 but launch only granted 76800 -> OOB write).
// 64x256-tile 256-thread GEMM for L2/L3; L3 single CTA covers N=256 ->
// h2 read once + fused head (fc 256->10) with DIRECT stores.
// L1 keeps conv-folded W1' with fp32-x loader.
// ---------------------------------------------------------------------------

#define BATCH 65536
#define K1P   832    // 784 padded to multiple of 64

// ---- scratch (__device__ globals; no allocations allowed) ----
__device__ __half g_h1[BATCH * 128];
__device__ __half g_h2[BATCH * 512];
__device__ __half g_w1[128 * K1P];      // folded conv+W1, fp16
__device__ __half g_w2[512 * 128];
__device__ __half g_w3[256 * 512];

// ---------------------------------------------------------------------------
// helpers
// ---------------------------------------------------------------------------
__device__ __forceinline__ uint32_t smem_u32(const void* p) {
    uint32_t a;
    asm("{ .reg .u64 t; cvta.to.shared.u64 t, %1; cvt.u32.u64 %0, t; }"
        : "=r"(a) : "l"(p));
    return a;
}
#define SWZ128(off) ((off) ^ (((off) >> 3) & 0x70))

#define CP_ASYNC16(saddr, gptr) \
    asm volatile("cp.async.cg.shared.global [%0], [%1], 16;" \
                 :: "r"(saddr), "l"(gptr) : "memory")
#define CP_COMMIT() asm volatile("cp.async.commit_group;" ::: "memory")
#define CP_WAIT0()  asm volatile("cp.async.wait_group 0;" ::: "memory")

#define LDSM_X4(r, addr) \
    asm volatile("ldmatrix.sync.aligned.m8n8.x4.shared.b16 {%0,%1,%2,%3}, [%4];" \
                 : "=r"((r)[0]), "=r"((r)[1]), "=r"((r)[2]), "=r"((r)[3]) \
                 : "r"(addr))

#define MMA_F16(d, a, b0, b1) \
    asm volatile("mma.sync.aligned.m16n8k16.row.col.f32.f16.f16.f32 " \
                 "{%0,%1,%2,%3}, {%4,%5,%6,%7}, {%8,%9}, {%0,%1,%2,%3};" \
                 : "+f"((d)[0]), "+f"((d)[1]), "+f"((d)[2]), "+f"((d)[3]) \
                 : "r"((a)[0]), "r"((a)[1]), "r"((a)[2]), "r"((a)[3]), \
                   "r"(b0), "r"(b1))

__device__ __forceinline__ unsigned pack_h2f(float a, float b) {
    return (unsigned)__half_as_ushort(__float2half_rn(a))
         | ((unsigned)__half_as_ushort(__float2half_rn(b)) << 16);
}

// ---------------------------------------------------------------------------
// wfold: W1'[n, pi*28+pj] = sum_{di,dj} W1[n,(pi-di)*26+(pj-dj)]*wc[3di+dj]
// ---------------------------------------------------------------------------
__global__ void wfold_kernel(const float* __restrict__ w1,
                             const float* __restrict__ wc,
                             __half* __restrict__ dst)
{
    int i = blockIdx.x * blockDim.x + threadIdx.x;
    if (i >= 128 * K1P) return;
    int n = i / K1P, p = i - n * K1P;
    float sum = 0.f;
    if (p < 784) {
        int pi = p / 28, pj = p - pi * 28;
        #pragma unroll
        for (int di = 0; di < 3; ++di) {
            #pragma unroll
            for (int dj = 0; dj < 3; ++dj) {
                int oi = pi - di, oj = pj - dj;
                if (oi >= 0 && oi < 26 && oj >= 0 && oj < 26)
                    sum += w1[n * 676 + oi * 26 + oj] * wc[di * 3 + dj];
            }
        }
    }
    dst[i] = __float2half_rn(sum);
}

__global__ void wcast_kernel(const float* __restrict__ src, int N, int Ks, int Kd,
                             __half* __restrict__ dst)
{
    int i = blockIdx.x * blockDim.x + threadIdx.x;
    if (i >= N * Kd) return;
    int n = i / Kd, k = i - n * Kd;
    float v = (k < Ks) ? src[(size_t)n * Ks + k] : 0.f;
    dst[i] = __float2half_rn(v);
}

// ---------------------------------------------------------------------------
// L1 GEMM (128 threads, 64x128): fp32 A (x) via LDG->cvt->STS reg double
// buffer; B (W1') via cp.async. K=832, logical A width 784. relu, fp16 out.
// ---------------------------------------------------------------------------
#define SM_A    0
#define SM_B    8192
#define BUF_STRIDE 24576
#define SM_BIAS (2 * BUF_STRIDE)
#define SMEM_SZ (SM_BIAS + 512)

__global__ void __launch_bounds__(128)
gemm_l1(const float* __restrict__ X,
        const __half* __restrict__ B,
        const float* __restrict__ bias,
        __half* __restrict__ outp)
{
    extern __shared__ __align__(1024) char smem[];
    const uint32_t sb = smem_u32(smem);
    const int tid  = threadIdx.x;
    const int wid  = tid >> 5;
    const int lane = tid & 31;
    const int m0   = blockIdx.y * 64;
    const int N    = 128;
    const int K    = K1P;
    float* bs = (float*)(smem + SM_BIAS);

    bs[tid] = bias[tid];

    const int arow  = tid >> 1;
    const int aColB = (tid & 1) * 32;
    const float* xrow = X + (size_t)(m0 + arow) * 784;
    uint32_t aSts[4];
    #pragma unroll
    for (int j = 0; j < 4; ++j)
        aSts[j] = SWZ128((uint32_t)arow * 128 + (uint32_t)((tid & 1) * 4 + j) * 16);

    uint32_t soB[8]; size_t gbOff[8];
    #pragma unroll
    for (int i = 0; i < 8; ++i) {
        const int idx = tid + 128 * i;
        const int row = idx >> 3, ch = idx & 7;
        soB[i]  = SWZ128((uint32_t)row * 128 + ch * 16);
        gbOff[i] = (size_t)row * K + ch * 8;
    }

    #pragma unroll
    for (int i = 0; i < 8; ++i)
        CP_ASYNC16(sb + SM_B + soB[i], B + gbOff[i]);
    CP_COMMIT();

    float4 xa[8];
    #pragma unroll
    for (int q = 0; q < 8; ++q) {
        const int col = aColB + q * 4;
        xa[q] = (col < 784) ? *(const float4*)(xrow + col)
                            : make_float4(0.f, 0.f, 0.f, 0.f);
    }

    const int wm = wid & 1;
    const int wn = wid >> 1;
    const int lrow  = lane & 15;
    const int lhalf = (lane >> 4) * 16;

    float acc[2][8][4];
    #pragma unroll
    for (int mi = 0; mi < 2; ++mi)
        #pragma unroll
        for (int nj = 0; nj < 8; ++nj)
            #pragma unroll
            for (int q = 0; q < 4; ++q) acc[mi][nj][q] = 0.f;

    int buf = 0;
    for (int kt = 0; kt < K; kt += 64) {
        #pragma unroll
        for (int j = 0; j < 4; ++j) {
            uint4 v;
            v.x = pack_h2f(xa[2 * j].x,     xa[2 * j].y);
            v.y = pack_h2f(xa[2 * j].z,     xa[2 * j].w);
            v.z = pack_h2f(xa[2 * j + 1].x, xa[2 * j + 1].y);
            v.w = pack_h2f(xa[2 * j + 1].z, xa[2 * j + 1].w);
            *(uint4*)(smem + (buf * BUF_STRIDE + SM_A) + aSts[j]) = v;
        }
        CP_WAIT0();
        __syncthreads();

        if (kt + 64 < K) {
            const uint32_t nb = sb + (buf ^ 1) * BUF_STRIDE;
            #pragma unroll
            for (int i = 0; i < 8; ++i)
                CP_ASYNC16(nb + SM_B + soB[i], B + gbOff[i] + kt + 64);
            CP_COMMIT();
            #pragma unroll
            for (int q = 0; q < 8; ++q) {
                const int col = kt + 64 + aColB + q * 4;
                xa[q] = (col < 784) ? *(const float4*)(xrow + col)
                                    : make_float4(0.f, 0.f, 0.f, 0.f);
            }
        }

        const uint32_t cb = sb + buf * BUF_STRIDE;
        #pragma unroll
        for (int ks = 0; ks < 4; ++ks) {
            const uint32_t kbyte = ks * 32 + lhalf;
            uint32_t av[2][4];
            #pragma unroll
            for (int mi = 0; mi < 2; ++mi) {
                const uint32_t row = wm * 32 + mi * 16 + lrow;
                LDSM_X4(av[mi], cb + SM_A + SWZ128(row * 128 + kbyte));
            }
            uint32_t bv[4][4];
            #pragma unroll
            for (int g = 0; g < 4; ++g) {
                const uint32_t row = wn * 64 + g * 16 + lrow;
                LDSM_X4(bv[g], cb + SM_B + SWZ128(row * 128 + kbyte));
            }
            #pragma unroll
            for (int mi = 0; mi < 2; ++mi) {
                #pragma unroll
                for (int nj = 0; nj < 8; ++nj) {
                    const int g = nj >> 1, h = nj & 1;
                    MMA_F16(acc[mi][nj], av[mi], bv[g][h], bv[g][h + 2]);
                }
            }
        }
        __syncthreads();
        buf ^= 1;
    }

    const int qr = lane >> 2;
    const int qc = (lane & 3) * 2;
    #pragma unroll
    for (int mi = 0; mi < 2; ++mi) {
        #pragma unroll
        for (int nj = 0; nj < 8; ++nj) {
            const int col = wn * 64 + nj * 8 + qc;
            const float b0 = bs[col], b1 = bs[col + 1];
            #pragma unroll
            for (int half = 0; half < 2; ++half) {
                const int row = wm * 32 + mi * 16 + qr + half * 8;
                float v0 = fmaxf(acc[mi][nj][half * 2 + 0] + b0, 0.f);
                float v1 = fmaxf(acc[mi][nj][half * 2 + 1] + b1, 0.f);
                *(uint32_t*)(outp + (size_t)(m0 + row) * N + col) =
                    pack_h2f(v0, v1);
            }
        }
    }
}

// ---------------------------------------------------------------------------
// 64x256-tile GEMM, 256 threads (8 warps, 32x64 each), BK=64, double-buffered
// cp.async. smem: buf0 [0,40960), buf1 [40960,81920), bias [81920,82944),
// b4 [82944,83008). HEAD epilogue reuses [0,65536) for the fp32 stage and
// [65536,75776) for w4 (both inside the dead buffers). Total 83008 bytes
// -> 2 CTAs/SM (166KB <= 228KB).
// HEAD=true: full h3 row resident -> fused fc(256->10), DIRECT stores.
// Requires: M%64==0, N%256==0, K%64==0.
// ---------------------------------------------------------------------------
#define G2_SM_A    0
#define G2_SM_B    8192
#define G2_STRIDE  40960
#define G2_BIAS    (2 * G2_STRIDE)              // 81920: 256 floats
#define G2_B4      (G2_BIAS + 1024)             // 82944: 16 floats
#define G2_W4      65536                        // HEAD: 10x256 fp32 stage reuse
#define G2_SMEM    (G2_B4 + 64)                 // 83008 bytes

template <bool RELU, bool HALF_OUT, bool HEAD>
__global__ void __launch_bounds__(256)
gemm256(const __half* __restrict__ A,
        const __half* __restrict__ B,
        const float* __restrict__ bias,
        void* __restrict__ outp,
        int N, int K,
        const float* __restrict__ w4p,
        const float* __restrict__ b4p)
{
    extern __shared__ __align__(1024) char smem[];
    const uint32_t sb = smem_u32(smem);
    const int tid  = threadIdx.x;
    const int wid  = tid >> 5;
    const int lane = tid & 31;
    const int m0   = blockIdx.y * 64;
    const int n0   = blockIdx.x * 256;
    float* bs  = (float*)(smem + G2_BIAS);
    float* b4s = (float*)(smem + G2_B4);

    bs[tid] = bias[n0 + tid];
    if (HEAD && tid < 10) b4s[tid] = b4p[tid];

    // ---- loaders: A 64 rows (2/thread), B 256 rows (8/thread) ----
    uint32_t soA[2]; size_t gaOff[2];
    #pragma unroll
    for (int i = 0; i < 2; ++i) {
        const int idx = tid + 256 * i;
        const int row = idx >> 3, ch = idx & 7;
        soA[i]  = SWZ128((uint32_t)row * 128 + ch * 16);
        gaOff[i] = (size_t)(m0 + row) * K + ch * 8;
    }
    uint32_t soB[8]; size_t gbOff[8];
    #pragma unroll
    for (int i = 0; i < 8; ++i) {
        const int idx = tid + 256 * i;
        const int row = idx >> 3, ch = idx & 7;
        soB[i]  = SWZ128((uint32_t)row * 128 + ch * 16);
        gbOff[i] = (size_t)(n0 + row) * K + ch * 8;
    }

    #pragma unroll
    for (int i = 0; i < 2; ++i)
        CP_ASYNC16(sb + G2_SM_A + soA[i], A + gaOff[i]);
    #pragma unroll
    for (int i = 0; i < 8; ++i)
        CP_ASYNC16(sb + G2_SM_B + soB[i], B + gbOff[i]);
    CP_COMMIT();

    // ---- warp tiling: wm in {0,1} (32 rows), wn in {0..3} (64 cols) ----
    const int wm = wid & 1;
    const int wn = wid >> 1;
    const int lrow  = lane & 15;
    const int lhalf = (lane >> 4) * 16;

    float acc[2][8][4];
    #pragma unroll
    for (int mi = 0; mi < 2; ++mi)
        #pragma unroll
        for (int nj = 0; nj < 8; ++nj)
            #pragma unroll
            for (int q = 0; q < 4; ++q) acc[mi][nj][q] = 0.f;

    int buf = 0;
    for (int kt = 0; kt < K; kt += 64) {
        CP_WAIT0();
        __syncthreads();

        if (kt + 64 < K) {
            const uint32_t nb = sb + (buf ^ 1) * G2_STRIDE;
            #pragma unroll
            for (int i = 0; i < 2; ++i)
                CP_ASYNC16(nb + G2_SM_A + soA[i], A + gaOff[i] + kt + 64);
            #pragma unroll
            for (int i = 0; i < 8; ++i)
                CP_ASYNC16(nb + G2_SM_B + soB[i], B + gbOff[i] + kt + 64);
            CP_COMMIT();
        }

        const uint32_t cb = sb + buf * G2_STRIDE;
        #pragma unroll
        for (int ks = 0; ks < 4; ++ks) {
            const uint32_t kbyte = ks * 32 + lhalf;
            uint32_t av[2][4];
            #pragma unroll
            for (int mi = 0; mi < 2; ++mi) {
                const uint32_t row = wm * 32 + mi * 16 + lrow;
                LDSM_X4(av[mi], cb + G2_SM_A + SWZ128(row * 128 + kbyte));
            }
            uint32_t bv[4][4];
            #pragma unroll
            for (int g = 0; g < 4; ++g) {
                const uint32_t row = wn * 64 + g * 16 + lrow;
                LDSM_X4(bv[g], cb + G2_SM_B + SWZ128(row * 128 + kbyte));
            }
            #pragma unroll
            for (int mi = 0; mi < 2; ++mi) {
                #pragma unroll
                for (int nj = 0; nj < 8; ++nj) {
                    const int g = nj >> 1, h = nj & 1;
                    MMA_F16(acc[mi][nj], av[mi], bv[g][h], bv[g][h + 2]);
                }
            }
        }
        __syncthreads();
        buf ^= 1;
    }

    const int qr = lane >> 2;
    const int qc = (lane & 3) * 2;

    if (HEAD) {
        // ---- fused head: stage full 64x256 relu tile, direct-store out ----
        float* stage = (float*)smem;               // [0, 65536)
        float* w4s   = (float*)(smem + G2_W4);     // [65536, 75776)
        #pragma unroll
        for (int i = tid; i < 2560; i += 256)
            w4s[i] = w4p[i];                        // w4 is 10x256, n0 == 0
        #pragma unroll
        for (int mi = 0; mi < 2; ++mi) {
            #pragma unroll
            for (int nj = 0; nj < 8; ++nj) {
                const int col = wn * 64 + nj * 8 + qc;
                const float b0 = bs[col], b1 = bs[col + 1];
                #pragma unroll
                for (int half = 0; half < 2; ++half) {
                    const int row = wm * 32 + mi * 16 + qr + half * 8;
                    stage[row * 256 + col]     = fmaxf(acc[mi][nj][half * 2 + 0] + b0, 0.f);
                    stage[row * 256 + col + 1] = fmaxf(acc[mi][nj][half * 2 + 1] + b1, 0.f);
                }
            }
        }
        __syncthreads();

        // each warp: 8 rows; lane covers 8 k-strides of 32
        float w4r[10][8];
        #pragma unroll
        for (int j = 0; j < 10; ++j)
            #pragma unroll
            for (int t = 0; t < 8; ++t)
                w4r[j][t] = w4s[j * 256 + lane + 32 * t];

        float* outF = (float*)outp;
        #pragma unroll 1
        for (int rr = 0; rr < 8; ++rr) {
            const int row = wid * 8 + rr;
            float xv[8];
            #pragma unroll
            for (int t = 0; t < 8; ++t)
                xv[t] = stage[row * 256 + lane + 32 * t];
            float pj[10];
            #pragma unroll
            for (int j = 0; j < 10; ++j) {
                float s = xv[0] * w4r[j][0];
                #pragma unroll
                for (int t = 1; t < 8; ++t)
                    s = fmaf(xv[t], w4r[j][t], s);
                #pragma unroll
                for (int off = 16; off > 0; off >>= 1)
                    s += __shfl_xor_sync(0xffffffffu, s, off);
                pj[j] = s;
            }
            if (lane == 0) {
                #pragma unroll
                for (int j = 0; j < 10; ++j)
                    outF[(size_t)(m0 + row) * 10 + j] = pj[j] + b4s[j];
            }
        }
    } else {
        #pragma unroll
        for (int mi = 0; mi < 2; ++mi) {
            #pragma unroll
            for (int nj = 0; nj < 8; ++nj) {
                const int col = wn * 64 + nj * 8 + qc;
                const float b0 = bs[col], b1 = bs[col + 1];
                #pragma unroll
                for (int half = 0; half < 2; ++half) {
                    const int row = wm * 32 + mi * 16 + qr + half * 8;
                    float v0 = acc[mi][nj][half * 2 + 0] + b0;
                    float v1 = acc[mi][nj][half * 2 + 1] + b1;
                    if (RELU) { v0 = fmaxf(v0, 0.f); v1 = fmaxf(v1, 0.f); }
                    const size_t g = (size_t)(m0 + row) * N + n0 + col;
                    if (HALF_OUT) {
                        *(uint32_t*)((__half*)outp + g) = pack_h2f(v0, v1);
                    } else {
                        *(float2*)((float*)outp + g) = make_float2(v0, v1);
                    }
                }
            }
        }
    }
}

// ---------------------------------------------------------------------------
// Launch
// ---------------------------------------------------------------------------
extern "C" void kernel_launch(void* const* d_in, const int* in_sizes, int n_in,
                              void* d_out, int out_size)
{
    const float* x  = (const float*)d_in[0];
    const float* wc = (const float*)d_in[1];
    const float* w1 = (const float*)d_in[2];
    const float* b1 = (const float*)d_in[3];
    const float* w2 = (const float*)d_in[4];
    const float* b2 = (const float*)d_in[5];
    const float* w3 = (const float*)d_in[6];
    const float* b3 = (const float*)d_in[7];
    const float* w4 = (const float*)d_in[8];
    const float* b4 = (const float*)d_in[9];
    float* out = (float*)d_out;

    __half *h1, *h2, *w1c, *w2c, *w3c;
    cudaGetSymbolAddress((void**)&h1,  g_h1);
    cudaGetSymbolAddress((void**)&h2,  g_h2);
    cudaGetSymbolAddress((void**)&w1c, g_w1);
    cudaGetSymbolAddress((void**)&w2c, g_w2);
    cudaGetSymbolAddress((void**)&w3c, g_w3);

    cudaFuncSetAttribute((const void*)gemm_l1,
                         cudaFuncAttributeMaxDynamicSharedMemorySize, SMEM_SZ);
    cudaFuncSetAttribute((const void*)gemm256<true, true, false>,
                         cudaFuncAttributeMaxDynamicSharedMemorySize, G2_SMEM);
    cudaFuncSetAttribute((const void*)gemm256<true, false, true>,
                         cudaFuncAttributeMaxDynamicSharedMemorySize, G2_SMEM);

    // weight prep (tiny)
    wfold_kernel<<<(128 * K1P + 255) / 256, 256>>>(w1, wc, w1c);
    wcast_kernel<<<(512 * 128 + 255) / 256, 256>>>(w2, 512, 128, 128, w2c);
    wcast_kernel<<<(256 * 512 + 255) / 256, 256>>>(w3, 256, 512, 512, w3c);

    // L1 (conv folded): relu([B,784(x)] x W1'^T) -> h1 (fp16)
    gemm_l1<<<dim3(1, BATCH / 64), 128, SMEM_SZ>>>(x, w1c, b1, h1);
    // L2: [B,128] x [512,128]^T -> relu -> h2 (fp16), N-tile 256
    gemm256<true, true, false><<<dim3(2, BATCH / 64), 256, G2_SMEM>>>(
        h1, w2c, b2, h2, 512, 128, nullptr, nullptr);
    // L3 + head: relu([B,512] x [256,512]^T) @ w4^T + b4 -> out (direct)
    gemm256<true, false, true><<<dim3(1, BATCH / 64), 256, G2_SMEM>>>(
        h2, w3c, b3, out, 256, 512, w4, b4);
}